// round 4
// baseline (speedup 1.0000x reference)
#include <cuda_runtime.h>
#include <math.h>

#define NIMG 12            // B*C = 4*3
#define N 256              // image / detector size
#define NA 180             // angles / proj dim
#define SINO_SZ (N*NA)     // 46080
#define NCHUNK 6           // backprojection angle chunks
#define CA (NA/NCHUNK)     // 30 angles per chunk
#define PI_D 3.14159265358979323846

// ---------------- device scratch (no allocations allowed) -------------------
__device__ float g_sino[NIMG*SINO_SZ];
__device__ float g_Q  [NIMG*SINO_SZ];
__device__ float g_Kp [NIMG*SINO_SZ];
__device__ float g_V  [NIMG*SINO_SZ];
__device__ float g_S  [NIMG*N*N];
__device__ float g_att[NIMG*SINO_SZ];
__device__ float g_flt[NIMG*SINO_SZ];
__device__ float g_part[NCHUNK*NIMG*N*N];

// ---------------- 1) forward radon (rotate-bilinear + column sums) ----------
// sino[n][p][a] = sum_y bilinear(img_n, sy(p,y), sx(p,y)),  cval=0 outside
__global__ void radon_kernel(const float* __restrict__ img)
{
    int a = blockIdx.x;          // angle
    int n = blockIdx.y;          // image
    int p = threadIdx.x;         // detector (x column of rotated image)

    float th = (float)((double)a * (PI_D / 180.0));
    float c = cosf(th), s = sinf(th);
    const float* im = img + n * N * N;

    float sx0 = c * (float)p - 128.f * (c + s - 1.f);
    float sy0 = -s * (float)p - 128.f * (c - s - 1.f);

    float acc = 0.f;
#pragma unroll 4
    for (int y = 0; y < N; y++) {
        float sx = fmaf(s, (float)y, sx0);
        float sy = fmaf(c, (float)y, sy0);
        float fx = floorf(sx), fy = floorf(sy);
        int x0 = (int)fx, y0 = (int)fy;
        float wx = sx - fx, wy = sy - fy;

        float v00 = 0.f, v01 = 0.f, v10 = 0.f, v11 = 0.f;
        bool x0v = (x0 >= 0) && (x0 < N);
        bool x1v = (x0 >= -1) && (x0 < N - 1);
        bool y0v = (y0 >= 0) && (y0 < N);
        bool y1v = (y0 >= -1) && (y0 < N - 1);
        if (y0v) {
            const float* r = im + y0 * N;
            if (x0v) v00 = __ldg(r + x0);
            if (x1v) v01 = __ldg(r + x0 + 1);
        }
        if (y1v) {
            const float* r = im + (y0 + 1) * N;
            if (x0v) v10 = __ldg(r + x0);
            if (x1v) v11 = __ldg(r + x0 + 1);
        }
        float top = (1.f - wx) * v00 + wx * v01;
        float bot = (1.f - wx) * v10 + wx * v11;
        acc += (1.f - wy) * top + wy * bot;
    }
    g_sino[n * SINO_SZ + p * NA + a] = acc;
}

// ---------------- 2) Q/K/V: out[n][i][j] = sum_a sino[n][i][a]*W[j][a]+b[j] -
__global__ void qkv_kernel(const float* __restrict__ W,
                           const float* __restrict__ b,
                           float* __restrict__ out)
{
    int n  = blockIdx.z;
    int i0 = blockIdx.y * 16;
    int j0 = blockIdx.x * 16;
    int tx = threadIdx.x, ty = threadIdx.y;
    int i = i0 + ty;         // < 256 always
    int j = j0 + tx;

    __shared__ float As[16][17];   // sino tile [i][a]
    __shared__ float Bs[16][17];   // W tile    [j][a]

    float acc = 0.f;
    for (int kt = 0; kt < NA; kt += 16) {
        int aa = kt + tx;
        As[ty][tx] = (aa < NA) ? g_sino[n * SINO_SZ + i * NA + aa] : 0.f;
        int jl = j0 + ty;
        Bs[ty][tx] = (jl < NA && aa < NA) ? W[jl * NA + aa] : 0.f;
        __syncthreads();
#pragma unroll
        for (int kk = 0; kk < 16; kk++)
            acc = fmaf(As[ty][kk], Bs[tx][kk], acc);
        __syncthreads();
    }
    if (j < NA)
        out[n * SINO_SZ + i * NA + j] = acc + b[j];
}

// ---------------- 3a) scores: S[n][i][k] = (Q[i].K[k]) / sqrt(180) ----------
__global__ void scores_kernel()
{
    int n  = blockIdx.z;
    int i0 = blockIdx.y * 16;
    int k0 = blockIdx.x * 16;
    int tx = threadIdx.x, ty = threadIdx.y;
    int i = i0 + ty;
    int k = k0 + tx;

    __shared__ float As[16][17];
    __shared__ float Bs[16][17];

    float acc = 0.f;
    for (int jt = 0; jt < NA; jt += 16) {
        int jj = jt + tx;
        As[ty][tx] = (jj < NA) ? g_Q [n * SINO_SZ + i * NA + jj] : 0.f;
        int kl = k0 + ty;
        Bs[ty][tx] = (jj < NA) ? g_Kp[n * SINO_SZ + kl * NA + jj] : 0.f;
        __syncthreads();
#pragma unroll
        for (int kk = 0; kk < 16; kk++)
            acc = fmaf(As[ty][kk], Bs[tx][kk], acc);
        __syncthreads();
    }
    g_S[n * N * N + i * N + k] = acc / sqrtf(180.f);
}

// ---------------- 3b) row softmax over S ------------------------------------
__global__ void softmax_kernel()
{
    int row = blockIdx.x;   // n*256 + i
    int tid = threadIdx.x;
    float v = g_S[row * N + tid];

    __shared__ float red[N];
    red[tid] = v;
    __syncthreads();
    for (int s = 128; s > 0; s >>= 1) {
        if (tid < s) red[tid] = fmaxf(red[tid], red[tid + s]);
        __syncthreads();
    }
    float mx = red[0];
    __syncthreads();
    float e = expf(v - mx);
    red[tid] = e;
    __syncthreads();
    for (int s = 128; s > 0; s >>= 1) {
        if (tid < s) red[tid] += red[tid + s];
        __syncthreads();
    }
    float sum = red[0];
    g_S[row * N + tid] = e / sum;
}

// ---------------- 3c) att[n][i][j] = sum_k P[i][k] * V[k][j] ---------------
__global__ void att_kernel()
{
    int n  = blockIdx.z;
    int i0 = blockIdx.y * 16;
    int j0 = blockIdx.x * 16;
    int tx = threadIdx.x, ty = threadIdx.y;
    int i = i0 + ty;
    int j = j0 + tx;

    __shared__ float As[16][17];   // P tile [i][k]
    __shared__ float Bs[16][17];   // V tile [k][j]

    float acc = 0.f;
    for (int kt = 0; kt < N; kt += 16) {
        As[ty][tx] = g_S[n * N * N + i * N + (kt + tx)];
        Bs[ty][tx] = (j < NA) ? g_V[n * SINO_SZ + (kt + ty) * NA + j] : 0.f;
        __syncthreads();
#pragma unroll
        for (int kk = 0; kk < 16; kk++)
            acc = fmaf(As[ty][kk], Bs[kk][tx], acc);
        __syncthreads();
    }
    if (j < NA)
        g_att[n * SINO_SZ + i * NA + j] = acc;
}

// ---------------- 4) ramp filter as Toeplitz GEMM ---------------------------
// filtered[n][m][a] = sum_k g((m-k) mod 512) * att[n][k][a]
// g = 2*f (f is even -> FFT-multiply == circular conv with 2f, exactly)
__global__ void filter_kernel()
{
    int n  = blockIdx.z;
    int m0 = blockIdx.y * 16;
    int a0 = blockIdx.x * 16;
    int tx = threadIdx.x, ty = threadIdx.y;
    int m = m0 + ty;
    int a = a0 + tx;
    int tid = ty * 16 + tx;

    __shared__ float gs[512];
    __shared__ float Bs[16][17];

    for (int d = tid; d < 512; d += 256) {
        float v = 0.f;
        if (d == 0) v = 0.5f;
        else if (d & 1) {
            int mm = (d <= 256) ? d : (512 - d);
            double pm = PI_D * (double)mm;
            v = (float)(-2.0 / (pm * pm));
        }
        gs[d] = v;
    }
    __syncthreads();

    float acc = 0.f;
    for (int kt = 0; kt < N; kt += 16) {
        Bs[ty][tx] = (a < NA) ? g_att[n * SINO_SZ + (kt + ty) * NA + a] : 0.f;
        __syncthreads();
#pragma unroll
        for (int kk = 0; kk < 16; kk++) {
            int d = (m - (kt + kk) + 512) & 511;
            acc = fmaf(gs[d], Bs[kk][tx], acc);
        }
        __syncthreads();
    }
    if (a < NA)
        g_flt[n * SINO_SZ + m * NA + a] = acc;
}

// ---------------- 5) backprojection (partial sums over angle chunks) --------
__global__ void backproj_kernel()
{
    int chunk = blockIdx.x;          // 0..5
    int rg    = blockIdx.y;          // row group of 32
    int n     = blockIdx.z;
    int tid   = threadIdx.x;         // = output column j
    int a0    = chunk * CA;

    __shared__ float colsm[CA * N];  // [a_local][m]
    __shared__ float cs[CA], sn[CA];

    // load filtered columns for this chunk (each thread: one m, 30 angles)
    {
        int m = tid;
        const float* src = g_flt + n * SINO_SZ + m * NA + a0;
        for (int al = 0; al < CA; al++)
            colsm[al * N + m] = src[al];
    }
    if (tid < CA) {
        float th = (float)((double)(a0 + tid) * (PI_D / 180.0));
        cs[tid] = cosf(th);
        sn[tid] = sinf(th);
    }
    __syncthreads();

    int j = tid;
    float fj = (float)j - 128.f;
    float* outp = g_part + (chunk * NIMG + n) * N * N;

    for (int r = 0; r < 32; r++) {
        int i = rg * 32 + r;
        float fi = (float)i - 128.f;
        float acc = 0.f;
#pragma unroll 5
        for (int al = 0; al < CA; al++) {
            float t = fj * cs[al] - fi * sn[al] + 128.f;
            float ft = floorf(t);
            int i0 = (int)ft;
            float frac = t - ft;
            int c0 = min(max(i0, 0), N - 1);
            int c1 = min(max(i0 + 1, 0), N - 1);
            float v0 = colsm[al * N + c0];
            float v1 = colsm[al * N + c1];
            float val = (1.f - frac) * v0 + frac * v1;
            if (t >= 0.f && t <= 255.f) acc += val;
        }
        outp[i * N + j] = acc;
    }
}

// ---------------- 6) reduce chunks + circle mask + scale --------------------
__global__ void reduce_kernel(float* __restrict__ out)
{
    int idx = blockIdx.x * blockDim.x + threadIdx.x;   // 0..786431
    int n = idx >> 16;
    int rem = idx & 0xFFFF;
    int i = rem >> 8;
    int j = rem & 0xFF;

    float s = 0.f;
#pragma unroll
    for (int c = 0; c < NCHUNK; c++)
        s += g_part[(c * NIMG + n) * N * N + rem];

    int di = i - 128, dj = j - 128;
    bool inside = (di * di + dj * dj) <= 128 * 128;
    out[idx] = inside ? s * (float)(PI_D / 360.0) : 0.f;
}

// ---------------- launch ----------------------------------------------------
extern "C" void kernel_launch(void* const* d_in, const int* in_sizes, int n_in,
                              void* d_out, int out_size)
{
    const float* x  = (const float*)d_in[0];
    const float* Wq = (const float*)d_in[1];
    const float* bq = (const float*)d_in[2];
    const float* Wk = (const float*)d_in[3];
    const float* bk = (const float*)d_in[4];
    const float* Wv = (const float*)d_in[5];
    const float* bv = (const float*)d_in[6];
    float* out = (float*)d_out;

    float *dQ, *dK, *dV;
    cudaGetSymbolAddress((void**)&dQ, g_Q);
    cudaGetSymbolAddress((void**)&dK, g_Kp);
    cudaGetSymbolAddress((void**)&dV, g_V);

    // 1) radon
    radon_kernel<<<dim3(NA, NIMG), N>>>(x);

    // 2) Q, K, V projections
    dim3 tb(16, 16);
    dim3 gqkv((NA + 15) / 16, N / 16, NIMG);
    qkv_kernel<<<gqkv, tb>>>(Wq, bq, dQ);
    qkv_kernel<<<gqkv, tb>>>(Wk, bk, dK);
    qkv_kernel<<<gqkv, tb>>>(Wv, bv, dV);

    // 3) attention
    scores_kernel<<<dim3(N / 16, N / 16, NIMG), tb>>>();
    softmax_kernel<<<NIMG * N, N>>>();
    att_kernel<<<gqkv, tb>>>();

    // 4) ramp filter (Toeplitz GEMM, exact circular-conv equivalent of FFT path)
    filter_kernel<<<dim3((NA + 15) / 16, N / 16, NIMG), tb>>>();

    // 5) backprojection partials
    backproj_kernel<<<dim3(NCHUNK, 8, NIMG), N>>>();

    // 6) reduce + mask + scale
    reduce_kernel<<<(NIMG * N * N) / 256, 256>>>(out);
}

// round 5
// speedup vs baseline: 1.8899x; 1.8899x over previous
#include <cuda_runtime.h>
#include <math.h>

#define NIMG 12
#define N 256
#define NA 180
#define SINO_SZ (N*NA)
#define NCHUNK 6
#define CA (NA/NCHUNK)
#define PI_D 3.14159265358979323846
#define PADO 54
#define PW 368
#define PH 366
#define SMS 68   // smem tile row stride (17 float4s -> 16B aligned rows)

// ---------------- device scratch ---------------------------------------
__device__ float2 g_pad2 [NIMG*PH*PW];   // (v(y,x), v(y,x+1))
__device__ float2 g_pad2T[NIMG*PH*PW];   // (v(y,x), v(y+1,x)) indexed [x][y]
__device__ float g_sino[NIMG*SINO_SZ];   // [n][a][p]  (angle-major)
__device__ float g_Q  [NIMG*SINO_SZ];    // [n][j][i]  (transposed)
__device__ float g_Kp [NIMG*SINO_SZ];    // [n][j][i]
__device__ float g_V  [NIMG*SINO_SZ];    // [n][i][j]
__device__ float g_S  [NIMG*N*N];        // [n][i][k]
__device__ float g_att[NIMG*SINO_SZ];    // [n][i][j]
__device__ float g_flt[NIMG*SINO_SZ];    // [n][a][m]  (angle-major!)
__device__ float g_part[NCHUNK*NIMG*N*N];

// ---------------- 0) build padded pair images ---------------------------
__global__ void pad2_kernel(const float* __restrict__ x)
{
    int idx = blockIdx.x * 256 + threadIdx.x;
    if (idx >= NIMG * PH * PW) return;
    int n   = idx / (PH * PW);
    int rem = idx - n * (PH * PW);
    int r   = rem / PW;
    int c   = rem - r * PW;
    const float* im = x + n * N * N;
    int ry = r - PADO, cx = c - PADO;

    float a0 = (ry >= 0 && ry < N && cx >= 0   && cx < N)   ? im[ry*N + cx]     : 0.f;
    float a1 = (ry >= 0 && ry < N && cx+1 >= 0 && cx+1 < N) ? im[ry*N + cx + 1] : 0.f;
    float b0 = (cx >= 0 && cx < N && ry >= 0   && ry < N)   ? im[cx*N + ry]     : 0.f;
    float b1 = (cx+1 >= 0 && cx+1 < N && ry >= 0 && ry < N) ? im[(cx+1)*N + ry] : 0.f;
    g_pad2 [idx] = make_float2(a0, a1);   // row = y, pair along x
    g_pad2T[idx] = make_float2(b0, b1);   // row = x, pair along y
}

// ---------------- 1) forward radon --------------------------------------
__global__ void radon_kernel()
{
    int a = blockIdx.x, n = blockIdx.y, p = threadIdx.x;
    float th = (float)((double)a * (PI_D / 180.0));
    float c = cosf(th), s = sinf(th);
    float sx0 = c * (float)p - 128.f * (c + s - 1.f) + (float)PADO;
    float sy0 = -s * (float)p - 128.f * (c - s - 1.f) + (float)PADO;

    float acc = 0.f;
    if (fabsf(s) <= fabsf(c)) {
        const float2* im = g_pad2 + n * PH * PW;
#pragma unroll 4
        for (int y = 0; y < N; y++) {
            float sx = fmaf(s, (float)y, sx0);
            float sy = fmaf(c, (float)y, sy0);
            int x0 = (int)sx, y0 = (int)sy;
            float wx = sx - (float)x0, wy = sy - (float)y0;
            float2 t0 = __ldg(im + y0 * PW + x0);
            float2 t1 = __ldg(im + (y0 + 1) * PW + x0);
            float top = fmaf(wx, t0.y - t0.x, t0.x);
            float bot = fmaf(wx, t1.y - t1.x, t1.x);
            acc += fmaf(wy, bot - top, top);
        }
    } else {
        const float2* im = g_pad2T + n * PH * PW;
#pragma unroll 4
        for (int y = 0; y < N; y++) {
            float sx = fmaf(s, (float)y, sx0);
            float sy = fmaf(c, (float)y, sy0);
            int x0 = (int)sx, y0 = (int)sy;
            float wx = sx - (float)x0, wy = sy - (float)y0;
            float2 q0 = __ldg(im + x0 * PW + y0);        // (v00, v10)
            float2 q1 = __ldg(im + (x0 + 1) * PW + y0);  // (v01, v11)
            float lft = fmaf(wy, q0.y - q0.x, q0.x);
            float rgt = fmaf(wy, q1.y - q1.x, q1.x);
            acc += fmaf(wx, rgt - lft, lft);
        }
    }
    g_sino[n * SINO_SZ + a * N + p] = acc;   // angle-major, coalesced
}

// ---------------- register-tiled 64x64 GEMM micro-kernel ----------------
__device__ __forceinline__ void mm16(const float* As, const float* Bs,
                                     float acc[4][4], int ty4, int tx4)
{
#pragma unroll
    for (int kk = 0; kk < 16; kk++) {
        float4 a = *reinterpret_cast<const float4*>(As + kk * SMS + ty4);
        float4 b = *reinterpret_cast<const float4*>(Bs + kk * SMS + tx4);
        float ar[4] = {a.x, a.y, a.z, a.w};
        float br[4] = {b.x, b.y, b.z, b.w};
#pragma unroll
        for (int i = 0; i < 4; i++)
#pragma unroll
            for (int j = 0; j < 4; j++)
                acc[i][j] = fmaf(ar[i], br[j], acc[i][j]);
    }
}

// ---------------- 2a) Q/K projection (transposed out): CT[j][i] ---------
// C[j][i] = sum_a W[j][a] * sinoT[a][i] + b[j]
__global__ void projT_kernel(const float* __restrict__ W,
                             const float* __restrict__ b,
                             float* __restrict__ out)
{
    int n  = blockIdx.z;
    int m0 = blockIdx.y * 64;   // j tile (180 -> 3 tiles)
    int n0 = blockIdx.x * 64;   // i tile (256 -> 4 tiles)
    int tx = threadIdx.x, ty = threadIdx.y;
    int tid = ty * 16 + tx;
    int ty4 = ty * 4, tx4 = tx * 4;
    __shared__ __align__(16) float As[16 * SMS];
    __shared__ __align__(16) float Bs[16 * SMS];
    const float* sT = g_sino + n * SINO_SZ;
    float acc[4][4] = {};

    for (int k0 = 0; k0 < 192; k0 += 16) {
#pragma unroll
        for (int i = 0; i < 4; i++) {
            int e = tid + i * 256;
            { int k = e & 15, m = e >> 4;      // transposed fill (W contiguous in a)
              int j = m0 + m, aa = k0 + k;
              As[k * SMS + m] = (j < NA && aa < NA) ? W[j * NA + aa] : 0.f; }
            { int m = e & 63, k = e >> 6;      // straight fill
              int aa = k0 + k;
              Bs[k * SMS + m] = (aa < NA) ? sT[aa * N + n0 + m] : 0.f; }
        }
        __syncthreads();
        mm16(As, Bs, acc, ty4, tx4);
        __syncthreads();
    }
#pragma unroll
    for (int r = 0; r < 4; r++) {
        int j = m0 + ty4 + r;
        if (j < NA) {
            float bv = b[j];
#pragma unroll
            for (int cc = 0; cc < 4; cc++)
                out[n * SINO_SZ + j * N + n0 + tx4 + cc] = acc[r][cc] + bv;
        }
    }
}

// ---------------- 2b) V projection (standard out): C[i][j] --------------
__global__ void projV_kernel(const float* __restrict__ W,
                             const float* __restrict__ b,
                             float* __restrict__ out)
{
    int n  = blockIdx.z;
    int m0 = blockIdx.y * 64;   // i tile (256 -> 4)
    int n0 = blockIdx.x * 64;   // j tile (180 -> 3)
    int tx = threadIdx.x, ty = threadIdx.y;
    int tid = ty * 16 + tx;
    int ty4 = ty * 4, tx4 = tx * 4;
    __shared__ __align__(16) float As[16 * SMS];
    __shared__ __align__(16) float Bs[16 * SMS];
    const float* sT = g_sino + n * SINO_SZ;
    float acc[4][4] = {};

    for (int k0 = 0; k0 < 192; k0 += 16) {
#pragma unroll
        for (int i = 0; i < 4; i++) {
            int e = tid + i * 256;
            { int m = e & 63, k = e >> 6;      // straight (sinoT contiguous in i)
              int aa = k0 + k;
              As[k * SMS + m] = (aa < NA) ? sT[aa * N + m0 + m] : 0.f; }
            { int k = e & 15, m = e >> 4;      // transposed (W contiguous in a)
              int j = n0 + m, aa = k0 + k;
              Bs[k * SMS + m] = (j < NA && aa < NA) ? W[j * NA + aa] : 0.f; }
        }
        __syncthreads();
        mm16(As, Bs, acc, ty4, tx4);
        __syncthreads();
    }
#pragma unroll
    for (int r = 0; r < 4; r++) {
        int i = m0 + ty4 + r;
#pragma unroll
        for (int cc = 0; cc < 4; cc++) {
            int j = n0 + tx4 + cc;
            if (j < NA) out[n * SINO_SZ + i * NA + j] = acc[r][cc] + b[j];
        }
    }
}

// ---------------- 3a) scores: S[i][k] = (Q.K)/sqrt(180) -----------------
__global__ void scores_kernel()
{
    int n  = blockIdx.z;
    int m0 = blockIdx.y * 64;   // i
    int n0 = blockIdx.x * 64;   // k_row
    int tx = threadIdx.x, ty = threadIdx.y;
    int tid = ty * 16 + tx;
    int ty4 = ty * 4, tx4 = tx * 4;
    __shared__ __align__(16) float As[16 * SMS];
    __shared__ __align__(16) float Bs[16 * SMS];
    const float* Qt = g_Q  + n * SINO_SZ;
    const float* Kt = g_Kp + n * SINO_SZ;
    float acc[4][4] = {};

    for (int k0 = 0; k0 < 192; k0 += 16) {
#pragma unroll
        for (int i = 0; i < 4; i++) {
            int e = tid + i * 256;
            int m = e & 63, k = e >> 6;
            int aa = k0 + k;
            As[k * SMS + m] = (aa < NA) ? Qt[aa * N + m0 + m] : 0.f;
            Bs[k * SMS + m] = (aa < NA) ? Kt[aa * N + n0 + m] : 0.f;
        }
        __syncthreads();
        mm16(As, Bs, acc, ty4, tx4);
        __syncthreads();
    }
    float inv = 1.f / sqrtf(180.f);
#pragma unroll
    for (int r = 0; r < 4; r++)
#pragma unroll
        for (int cc = 0; cc < 4; cc++)
            g_S[n * N * N + (m0 + ty4 + r) * N + n0 + tx4 + cc] = acc[r][cc] * inv;
}

// ---------------- 3b) row softmax ---------------------------------------
__global__ void softmax_kernel()
{
    int row = blockIdx.x;
    int tid = threadIdx.x;
    float v = g_S[row * N + tid];
    __shared__ float red[N];
    red[tid] = v;
    __syncthreads();
    for (int s = 128; s > 0; s >>= 1) {
        if (tid < s) red[tid] = fmaxf(red[tid], red[tid + s]);
        __syncthreads();
    }
    float mx = red[0];
    __syncthreads();
    float e = expf(v - mx);
    red[tid] = e;
    __syncthreads();
    for (int s = 128; s > 0; s >>= 1) {
        if (tid < s) red[tid] += red[tid + s];
        __syncthreads();
    }
    g_S[row * N + tid] = e / red[0];
}

// ---------------- 3c) att[i][j] = P @ V ---------------------------------
__global__ void att_kernel()
{
    int n  = blockIdx.z;
    int m0 = blockIdx.y * 64;   // i (4)
    int n0 = blockIdx.x * 64;   // j (3)
    int tx = threadIdx.x, ty = threadIdx.y;
    int tid = ty * 16 + tx;
    int ty4 = ty * 4, tx4 = tx * 4;
    __shared__ __align__(16) float As[16 * SMS];
    __shared__ __align__(16) float Bs[16 * SMS];
    float acc[4][4] = {};

    for (int k0 = 0; k0 < N; k0 += 16) {
#pragma unroll
        for (int i = 0; i < 4; i++) {
            int e = tid + i * 256;
            { int k = e & 15, m = e >> 4;  // transposed (S contiguous in k)
              As[k * SMS + m] = g_S[n * N * N + (m0 + m) * N + k0 + k]; }
            { int m = e & 63, k = e >> 6;  // straight (V contiguous in j)
              Bs[k * SMS + m] = (n0 + m < NA) ? g_V[n * SINO_SZ + (k0 + k) * NA + n0 + m] : 0.f; }
        }
        __syncthreads();
        mm16(As, Bs, acc, ty4, tx4);
        __syncthreads();
    }
#pragma unroll
    for (int r = 0; r < 4; r++)
#pragma unroll
        for (int cc = 0; cc < 4; cc++) {
            int j = n0 + tx4 + cc;
            if (j < NA) g_att[n * SINO_SZ + (m0 + ty4 + r) * NA + j] = acc[r][cc];
        }
}

// ---------------- 4) ramp filter (Toeplitz GEMM), out angle-major --------
// flt[a][m] = sum_k att[k][a] * g((m-k) & 511)
__global__ void filter_kernel()
{
    int n  = blockIdx.z;
    int m0 = blockIdx.y * 64;   // a tile (3)
    int n0 = blockIdx.x * 64;   // m tile (4)
    int tx = threadIdx.x, ty = threadIdx.y;
    int tid = ty * 16 + tx;
    int ty4 = ty * 4, tx4 = tx * 4;
    __shared__ __align__(16) float As[16 * SMS];
    __shared__ __align__(16) float Bs[16 * SMS];
    __shared__ float gs[512];

    for (int d = tid; d < 512; d += 256) {
        float v = 0.f;
        if (d == 0) v = 0.5f;
        else if (d & 1) {
            int mm = (d <= 256) ? d : (512 - d);
            double pm = PI_D * (double)mm;
            v = (float)(-2.0 / (pm * pm));
        }
        gs[d] = v;
    }
    __syncthreads();

    float acc[4][4] = {};
    for (int k0 = 0; k0 < N; k0 += 16) {
#pragma unroll
        for (int i = 0; i < 4; i++) {
            int e = tid + i * 256;
            int m = e & 63, k = e >> 6;
            As[k * SMS + m] = (m0 + m < NA) ? g_att[n * SINO_SZ + (k0 + k) * NA + m0 + m] : 0.f;
            Bs[k * SMS + m] = gs[((n0 + m) - (k0 + k)) & 511];
        }
        __syncthreads();
        mm16(As, Bs, acc, ty4, tx4);
        __syncthreads();
    }
#pragma unroll
    for (int r = 0; r < 4; r++) {
        int a = m0 + ty4 + r;
        if (a < NA)
#pragma unroll
            for (int cc = 0; cc < 4; cc++)
                g_flt[n * SINO_SZ + a * N + n0 + tx4 + cc] = acc[r][cc];
    }
}

// ---------------- 5) backprojection (padded smem, coalesced loads) ------
__global__ void backproj_kernel()
{
    int chunk = blockIdx.x, rg = blockIdx.y, n = blockIdx.z;
    int tid = threadIdx.x;
    int a0 = chunk * CA;

    __shared__ float colsm[CA][368];   // padded by 55 each side (55+256+57)
    __shared__ float cs[CA], sn[CA];

    for (int idx = tid; idx < CA * 368; idx += 256) {
        int al = idx / 368;
        int mp = idx - al * 368;
        int m = mp - 55;
        colsm[al][mp] = (m >= 0 && m < N) ? g_flt[n * SINO_SZ + (a0 + al) * N + m] : 0.f;
    }
    if (tid < CA) {
        float th = (float)((double)(a0 + tid) * (PI_D / 180.0));
        cs[tid] = cosf(th);
        sn[tid] = sinf(th);
    }
    __syncthreads();

    int j = tid;
    float fj = (float)j - 128.f;
    float* outp = g_part + (chunk * NIMG + n) * N * N;

    for (int r = 0; r < 32; r++) {
        int i = rg * 32 + r;
        float fi = (float)i - 128.f;
        float acc = 0.f;
#pragma unroll 6
        for (int al = 0; al < CA; al++) {
            float t = fj * cs[al] - fi * sn[al] + 183.f;   // +128 +55 pad
            int i0 = (int)t;
            float frac = t - (float)i0;
            float v0 = colsm[al][i0];
            float v1 = colsm[al][i0 + 1];
            float val = fmaf(frac, v1 - v0, v0);
            bool inb = (t >= 55.f) && (t <= 310.f);
            acc += inb ? val : 0.f;
        }
        outp[i * N + j] = acc;
    }
}

// ---------------- 6) reduce + circle mask + scale -----------------------
__global__ void reduce_kernel(float* __restrict__ out)
{
    int idx = blockIdx.x * blockDim.x + threadIdx.x;
    int n = idx >> 16;
    int rem = idx & 0xFFFF;
    int i = rem >> 8;
    int j = rem & 0xFF;
    float s = 0.f;
#pragma unroll
    for (int c = 0; c < NCHUNK; c++)
        s += g_part[(c * NIMG + n) * N * N + rem];
    int di = i - 128, dj = j - 128;
    bool inside = (di * di + dj * dj) <= 128 * 128;
    out[idx] = inside ? s * (float)(PI_D / 360.0) : 0.f;
}

// ---------------- launch ------------------------------------------------
extern "C" void kernel_launch(void* const* d_in, const int* in_sizes, int n_in,
                              void* d_out, int out_size)
{
    const float* x  = (const float*)d_in[0];
    const float* Wq = (const float*)d_in[1];
    const float* bq = (const float*)d_in[2];
    const float* Wk = (const float*)d_in[3];
    const float* bk = (const float*)d_in[4];
    const float* Wv = (const float*)d_in[5];
    const float* bv = (const float*)d_in[6];
    float* out = (float*)d_out;

    float *dQ, *dK, *dV;
    cudaGetSymbolAddress((void**)&dQ, g_Q);
    cudaGetSymbolAddress((void**)&dK, g_Kp);
    cudaGetSymbolAddress((void**)&dV, g_V);

    dim3 tb(16, 16);

    pad2_kernel<<<(NIMG * PH * PW + 255) / 256, 256>>>(x);
    radon_kernel<<<dim3(NA, NIMG), N>>>();

    projT_kernel<<<dim3(4, 3, NIMG), tb>>>(Wq, bq, dQ);
    projT_kernel<<<dim3(4, 3, NIMG), tb>>>(Wk, bk, dK);
    projV_kernel<<<dim3(3, 4, NIMG), tb>>>(Wv, bv, dV);

    scores_kernel<<<dim3(4, 4, NIMG), tb>>>();
    softmax_kernel<<<NIMG * N, N>>>();
    att_kernel<<<dim3(3, 4, NIMG), tb>>>();

    filter_kernel<<<dim3(4, 3, NIMG), tb>>>();

    backproj_kernel<<<dim3(NCHUNK, 8, NIMG), N>>>();
    reduce_kernel<<<(NIMG * N * N) / 256, 256>>>(out);
}